// round 1
// baseline (speedup 1.0000x reference)
#include <cuda_runtime.h>
#include <math.h>

#define NROWS 100000
#define DIMS  1443
#define NQ    (NROWS/4)       // 25000 rows per alignment phase
#define FBLOCKS 256

// ---------------- device scratch (allocation-free) ----------------
__device__ float    g_part[3][NROWS][4];   // per-warp GEMV partials
__device__ float    g_yv[3][NROWS];        // y1,y2,y3
__device__ float    g_prod[NROWS];         // running score product
__device__ unsigned g_key[NROWS];          // radix keys of current round
__device__ unsigned g_hist[6][65536];      // 2 passes x 3 rounds
__device__ unsigned g_prefix[3];
__device__ int      g_need[3];
__device__ int      g_tie[3];
__device__ float    g_inv[3];              // 1/||w||
__device__ float    g_coef[NROWS];         // final per-row coefficient (0 if unselected)
__device__ float    g_fpart[FBLOCKS][DIMS];

__device__ __forceinline__ unsigned f2key(float f) {
    unsigned u = __float_as_uint(f);
    return (u & 0x80000000u) ? ~u : (u | 0x80000000u);
}

// ---------------- init: norms + zero hists/counters ----------------
__global__ void k_init(const float* __restrict__ w1, const float* __restrict__ w2,
                       const float* __restrict__ w3) {
    int b = blockIdx.x;
    if (b < 3) {
        const float* w = (b == 0) ? w1 : ((b == 1) ? w2 : w3);
        float s = 0.f;
        for (int i = threadIdx.x; i < DIMS; i += blockDim.x) { float v = w[i]; s += v * v; }
        __shared__ float sh[256];
        sh[threadIdx.x] = s; __syncthreads();
        for (int off = 128; off > 0; off >>= 1) {
            if (threadIdx.x < off) sh[threadIdx.x] += sh[threadIdx.x + off];
            __syncthreads();
        }
        if (threadIdx.x == 0) {
            g_inv[b] = 1.0f / sqrtf(sh[0]);
            g_prefix[b] = 0u;
            g_tie[b] = 0;
            g_need[b] = (b == 0) ? 50000 : ((b == 1) ? 25000 : 12500);
        }
    } else {
        unsigned* h = &g_hist[0][0];
        const int total = 6 * 65536;
        for (int i = (b - 3) * blockDim.x + threadIdx.x; i < total;
             i += (gridDim.x - 3) * blockDim.x) h[i] = 0u;
    }
}

// ---------------- fused 3-way GEMV (phase-specialized, LDG.128) ----------------
#define GR 25
__global__ void __launch_bounds__(128) k_gemv(const float* __restrict__ x,
                                              const float* __restrict__ w1,
                                              const float* __restrict__ w2,
                                              const float* __restrict__ w3) {
    const int t = threadIdx.x;
    const int phase = blockIdx.x & 3;
    const int jb = blockIdx.x >> 2;
    const int a = phase;                       // peel offset so (row*1443 + a) is 16B-aligned
    const int m2 = t + 256;
    const bool has2 = (m2 < 360);

    const float* ws[3] = { w1, w2, w3 };
    float wr[3][3][4];
#pragma unroll
    for (int wv = 0; wv < 3; wv++) {
#pragma unroll
        for (int c = 0; c < 3; c++) {
            int m = t + c * 128;
            bool ok = (m < 360);
            int col = a + 4 * m;
#pragma unroll
            for (int e = 0; e < 4; e++)
                wr[wv][c][e] = ok ? __ldg(ws[wv] + col + e) : 0.0f;
        }
    }
    // 3 leftover scalar columns (head 0..a-1 and tail a+1440..1442) -> threads 120..122
    int eidx = t - 120;
    bool haveE = (eidx >= 0 && eidx < 3);
    int ecol = 0; float we0 = 0.f, we1 = 0.f, we2 = 0.f;
    if (haveE) {
        ecol = (eidx < a) ? eidx : (a + 1440 + (eidx - a));
        we0 = __ldg(w1 + ecol); we1 = __ldg(w2 + ecol); we2 = __ldg(w3 + ecol);
    }

    for (int jj = 0; jj < GR; jj++) {
        int j = jb * GR + jj;
        int row = phase + 4 * j;
        const float* rx = x + (long)row * DIMS;
        const float4* p = (const float4*)(rx + a);
        float4 v0 = __ldg(p + t);
        float4 v1 = __ldg(p + t + 128);
        float4 v2 = has2 ? __ldg(p + m2) : make_float4(0.f, 0.f, 0.f, 0.f);
        float s0, s1, s2;
        {
            float4 v[3] = { v0, v1, v2 };
            float acc[3] = { 0.f, 0.f, 0.f };
#pragma unroll
            for (int c = 0; c < 3; c++) {
#pragma unroll
                for (int wv = 0; wv < 3; wv++) {
                    acc[wv] += v[c].x * wr[wv][c][0] + v[c].y * wr[wv][c][1]
                             + v[c].z * wr[wv][c][2] + v[c].w * wr[wv][c][3];
                }
            }
            s0 = acc[0]; s1 = acc[1]; s2 = acc[2];
        }
        if (haveE) {
            float xv = __ldg(rx + ecol);
            s0 += xv * we0; s1 += xv * we1; s2 += xv * we2;
        }
#pragma unroll
        for (int off = 16; off > 0; off >>= 1) {
            s0 += __shfl_down_sync(0xffffffffu, s0, off);
            s1 += __shfl_down_sync(0xffffffffu, s1, off);
            s2 += __shfl_down_sync(0xffffffffu, s2, off);
        }
        if ((t & 31) == 0) {
            int w = t >> 5;
            g_part[0][row][w] = s0;
            g_part[1][row][w] = s1;
            g_part[2][row][w] = s2;
        }
    }
}

// ---------------- finalize y + round-1 keys ----------------
__global__ void k_keybuild() {
    int i = blockIdx.x * blockDim.x + threadIdx.x;
    if (i >= NROWS) return;
    float y[3];
#pragma unroll
    for (int w = 0; w < 3; w++) {
        float4 pv = *(const float4*)&g_part[w][i][0];
        y[w] = pv.x + pv.y + pv.z + pv.w;
        g_yv[w][i] = y[w];
    }
    g_key[i] = f2key(y[0]);   // monotone with tanh(y1/||w1||)
}

// ---------------- radix-select histogram pass ----------------
__global__ void k_hist(int pass, int r, int h) {
    int i = blockIdx.x * blockDim.x + threadIdx.x;
    if (i >= NROWS) return;
    unsigned k = g_key[i];
    if (pass == 0) {
        if (k == 0u) return;  // inactive rows: skip (avoid single-address atomic hotspot)
        atomicAdd(&g_hist[h][k >> 16], 1u);
    } else {
        if ((k >> 16) == (g_prefix[r] >> 16))
            atomicAdd(&g_hist[h][k & 0xffffu], 1u);
    }
}

// ---------------- radix-select scan pass (1 block) ----------------
__global__ void k_scan(int r, int h, int shift) {
    __shared__ unsigned csum[1024];
    const int t = threadIdx.x;
    const int need = g_need[r];             // read before any write (syncs below order it)
    const int base = 65535 - (t << 6);
    const unsigned* hist = g_hist[h];
    unsigned s = 0;
#pragma unroll 8
    for (int i = 0; i < 64; i++) s += hist[base - i];
    csum[t] = s;
    __syncthreads();
    for (int off = 1; off < 1024; off <<= 1) {
        unsigned tmp = (t >= off) ? csum[t - off] : 0u;
        __syncthreads();
        csum[t] += tmp;
        __syncthreads();
    }
    unsigned incl = csum[t];
    unsigned before = incl - s;
    if ((int)before < need && need <= (int)incl) {
        unsigned acc = before;
        for (int i = 0; i < 64; i++) {
            unsigned c = hist[base - i];
            if ((int)(acc + c) >= need) {
                g_prefix[r] |= ((unsigned)(base - i)) << shift;
                g_need[r] = need - (int)acc;
                break;
            }
            acc += c;
        }
    }
}

// ---------------- per-round select ----------------
__global__ void k_select(int r) {
    int i = blockIdx.x * blockDim.x + threadIdx.x;
    if (i >= NROWS) return;
    unsigned key = g_key[i];
    unsigned T = g_prefix[r];
    bool sel;
    if (key > T)       sel = true;
    else if (key == T) sel = (atomicAdd(&g_tie[r], 1) < g_need[r]);
    else               sel = false;

    if (r == 0) {
        if (sel) {
            float s1 = tanhf(g_yv[0][i] * g_inv[0]);
            g_prod[i] = s1;
            g_key[i] = f2key(s1 * g_yv[1][i]);
        } else g_key[i] = 0u;
    } else if (r == 1) {
        if (sel) {
            float p = g_prod[i];
            float s2 = tanhf(p * g_yv[1][i] * g_inv[1]);
            float p2 = p * s2;
            g_prod[i] = p2;
            g_key[i] = f2key(p2 * g_yv[2][i]);
        } else g_key[i] = 0u;
    } else {
        float c = 0.f;
        if (sel) {
            float p2 = g_prod[i];
            float s3 = tanhf(p2 * g_yv[2][i] * g_inv[2]);
            c = p2 * s3 * (1.0f / 12500.0f);
        }
        g_coef[i] = c;
    }
}

// ---------------- weighted gather-reduce, stage 1 (deterministic partials) ----------------
__global__ void __launch_bounds__(384) k_final1(const float* __restrict__ x) {
    const int bid = blockIdx.x;            // 0..255
    const int phase = bid & 3;
    const int seg = bid >> 2;              // 0..63
    const int t = threadIdx.x;
    const int a = phase;
    const int jlo = (seg * NQ) / 64, jhi = ((seg + 1) * NQ) / 64;
    float acc0 = 0.f, acc1 = 0.f, acc2 = 0.f, acc3 = 0.f;
    const bool isVec = (t < 360);
    const int eidx = t - 360;
    const bool isE = (eidx >= 0 && eidx < 3);
    const int ecol = isE ? ((eidx < a) ? eidx : (a + 1440 + (eidx - a))) : 0;

    for (int j = jlo; j < jhi; j++) {
        int row = phase + 4 * j;
        float c = g_coef[row];
        if (c == 0.0f) continue;
        const float* rx = x + (long)row * DIMS;
        if (isVec) {
            float4 v = __ldg((const float4*)(rx + a) + t);
            acc0 += c * v.x; acc1 += c * v.y; acc2 += c * v.z; acc3 += c * v.w;
        } else if (isE) {
            acc0 += c * __ldg(rx + ecol);
        }
    }
    if (isVec) {
        int d = a + 4 * t;
        g_fpart[bid][d]     = acc0;
        g_fpart[bid][d + 1] = acc1;
        g_fpart[bid][d + 2] = acc2;
        g_fpart[bid][d + 3] = acc3;
    } else if (isE) {
        g_fpart[bid][ecol] = acc0;
    }
}

// ---------------- stage 2: fixed-order final sum ----------------
__global__ void k_final2(float* __restrict__ out) {
    int d = blockIdx.x * blockDim.x + threadIdx.x;
    if (d >= DIMS) return;
    float s = 0.f;
#pragma unroll 8
    for (int b = 0; b < FBLOCKS; b++) s += g_fpart[b][d];
    out[d] = s;
}

// ---------------- launch ----------------
extern "C" void kernel_launch(void* const* d_in, const int* in_sizes, int n_in,
                              void* d_out, int out_size) {
    const float* x  = (const float*)d_in[0];
    // d_in[1] edge_index (int64), d_in[2] edge_attr: dead inputs
    const float* w1 = (const float*)d_in[3];
    const float* w2 = (const float*)d_in[4];
    const float* w3 = (const float*)d_in[5];
    float* out = (float*)d_out;

    k_init<<<195, 256>>>(w1, w2, w3);
    k_gemv<<<4 * (NQ / GR), 128>>>(x, w1, w2, w3);
    k_keybuild<<<(NROWS + 255) / 256, 256>>>();

    const int gsel = (NROWS + 255) / 256;
    for (int r = 0; r < 3; r++) {
        k_hist<<<gsel, 256>>>(0, r, 2 * r);
        k_scan<<<1, 1024>>>(r, 2 * r, 16);
        k_hist<<<gsel, 256>>>(1, r, 2 * r + 1);
        k_scan<<<1, 1024>>>(r, 2 * r + 1, 0);
        k_select<<<gsel, 256>>>(r);
    }

    k_final1<<<FBLOCKS, 384>>>(x);
    k_final2<<<(DIMS + 255) / 256, 256>>>(out);
}

// round 2
// speedup vs baseline: 1.2737x; 1.2737x over previous
#include <cuda_runtime.h>
#include <math.h>

#define NROWS 100000
#define DIMS  1443
#define NB    148
#define NT    512
#define NWARP 16
#define TOTW  (NB*NWARP)          // 2368 warps
#define CANDCAP 4096
#define WPACK_BYTES (4*3*360*16)  // 69120

// ---------------- device scratch (allocation-free) ----------------
__device__ unsigned g_bar = 0;
__device__ float    g_y1[NROWS], g_y2[NROWS], g_y3[NROWS];
__device__ float    g_prod[NROWS];
__device__ float    g_coef[NROWS];
__device__ unsigned g_key[NROWS];
__device__ unsigned g_hist[3][65536];
__device__ unsigned g_candk[NROWS];
__device__ int      g_candr[NROWS];
__device__ int      g_ncand;
__device__ unsigned g_Bsel;
__device__ int      g_needB;
__device__ float    g_fpart[TOTW][DIMS];   // per-warp gather partials
__device__ float    g_epart[16][DIMS];     // reduce stage-1 partials

__device__ __forceinline__ unsigned f2key(float f) {
    unsigned u = __float_as_uint(f);
    return (u & 0x80000000u) ? ~u : (u | 0x80000000u);
}

// software grid barrier: monotone counter, absolute per-phase targets.
// __threadfence (gpu scope) emits CCTL.IVALL on sm_103a -> flushes L1D,
// so post-barrier loads see remote writes even without .cg.
__device__ __forceinline__ void gbar(unsigned ph) {
    __syncthreads();
    if (threadIdx.x == 0) {
        __threadfence();
        atomicAdd(&g_bar, 1u);
        const unsigned tgt = ph * NB;
        while (atomicAdd(&g_bar, 0u) < tgt) __nanosleep(128);
        __threadfence();
    }
    __syncthreads();
}

__device__ __forceinline__ void upd(int r, int i, bool sel,
                                    float i1, float i2, float i3) {
    if (r == 0) {
        if (sel) {
            float y = g_y1[i];
            float s = tanhf(y * i1);
            g_prod[i] = s;
            g_key[i] = f2key(s * g_y2[i]);
        } else g_key[i] = 0u;
    } else if (r == 1) {
        if (sel) {
            float p = __ldcg(&g_prod[i]);
            float s = tanhf(p * g_y2[i] * i2);
            p *= s;
            g_prod[i] = p;
            g_key[i] = f2key(p * g_y3[i]);
        } else g_key[i] = 0u;
    } else {
        float cf = 0.f;
        if (sel) {
            float p = __ldcg(&g_prod[i]);
            float s = tanhf(p * g_y3[i] * i3);
            cf = p * s * (1.0f / 12500.0f);
        }
        g_coef[i] = cf;
    }
}

extern __shared__ float4 s_wp[];   // [4 phases][3 vecs][360 float4]

__global__ void __launch_bounds__(NT, 2) k_persist(
    const float* __restrict__ x,
    const float* __restrict__ w1, const float* __restrict__ w2,
    const float* __restrict__ w3, float* __restrict__ out)
{
    const int tid  = threadIdx.x, bid = blockIdx.x;
    const int lane = tid & 31,    wid = tid >> 5;
    const int gw   = bid * NWARP + wid;
    const int gtid = bid * NT + tid;

    __shared__ float    s_n[3][NWARP];
    __shared__ float    s_inv[3];
    __shared__ unsigned s_scan[NT];
    __shared__ unsigned s_ck[CANDCAP];
    __shared__ int      s_cr[CANDCAP];

    // ---- w norms (computed redundantly per block; block-local) ----
    {
        float a0 = 0.f, a1 = 0.f, a2 = 0.f;
        for (int i = tid; i < DIMS; i += NT) {
            float v1 = __ldg(w1 + i), v2 = __ldg(w2 + i), v3 = __ldg(w3 + i);
            a0 += v1 * v1; a1 += v2 * v2; a2 += v3 * v3;
        }
#pragma unroll
        for (int off = 16; off > 0; off >>= 1) {
            a0 += __shfl_down_sync(0xffffffffu, a0, off);
            a1 += __shfl_down_sync(0xffffffffu, a1, off);
            a2 += __shfl_down_sync(0xffffffffu, a2, off);
        }
        if (lane == 0) { s_n[0][wid] = a0; s_n[1][wid] = a1; s_n[2][wid] = a2; }
        __syncthreads();
        if (tid < 3) {
            float s = 0.f;
            for (int w = 0; w < NWARP; w++) s += s_n[tid][w];
            s_inv[tid] = 1.0f / sqrtf(s);
        }
    }

    // ---- fill w-pack (4 alignment phases) + zero hists ----
    for (int idx = tid; idx < 4 * 3 * 360; idx += NT) {
        int a = idx / 1080, rem = idx % 1080;
        int v = rem / 360,  m   = rem % 360;
        const float* w = (v == 0) ? w1 : ((v == 1) ? w2 : w3);
        int col = a + 4 * m;   // col+3 <= 1442 always
        s_wp[idx] = make_float4(__ldg(w + col), __ldg(w + col + 1),
                                __ldg(w + col + 2), __ldg(w + col + 3));
    }
    for (int i = gtid; i < 3 * 65536; i += NB * NT)
        ((unsigned*)g_hist)[i] = 0u;
    __syncthreads();

    const float i1 = s_inv[0], i2 = s_inv[1], i3 = s_inv[2];

    // ---------------- phase B: fused 3-way GEMV, row per warp ----------------
    {
        const int a = gw & 3;    // row stride 2368 == 0 mod 4 -> fixed phase
        const float4* wpa = s_wp + (a * 3 + 0) * 360;
        const float4* wpb = s_wp + (a * 3 + 1) * 360;
        const float4* wpc = s_wp + (a * 3 + 2) * 360;
        const int e = lane - 8;
        const bool haveE = (e >= 0 && e < 3);
        int ecol = 0; float we1 = 0.f, we2 = 0.f, we3 = 0.f;
        if (haveE) {
            ecol = (e < a) ? e : a + 1440 + (e - a);
            we1 = __ldg(w1 + ecol); we2 = __ldg(w2 + ecol); we3 = __ldg(w3 + ecol);
        }
        for (int row = gw; row < NROWS; row += TOTW) {
            const float4* px = (const float4*)(x + (size_t)row * DIMS + a);
            float s0 = 0.f, s1 = 0.f, s2 = 0.f;
#pragma unroll
            for (int k = 0; k < 11; k++) {
                int m = lane + 32 * k;
                float4 v = __ldg(px + m);
                float4 ua = wpa[m], ub = wpb[m], uc = wpc[m];
                s0 += v.x * ua.x + v.y * ua.y + v.z * ua.z + v.w * ua.w;
                s1 += v.x * ub.x + v.y * ub.y + v.z * ub.z + v.w * ub.w;
                s2 += v.x * uc.x + v.y * uc.y + v.z * uc.z + v.w * uc.w;
            }
            if (lane < 8) {
                int m = 352 + lane;
                float4 v = __ldg(px + m);
                float4 ua = wpa[m], ub = wpb[m], uc = wpc[m];
                s0 += v.x * ua.x + v.y * ua.y + v.z * ua.z + v.w * ua.w;
                s1 += v.x * ub.x + v.y * ub.y + v.z * ub.z + v.w * ub.w;
                s2 += v.x * uc.x + v.y * uc.y + v.z * uc.z + v.w * uc.w;
            }
            if (haveE) {
                float xv = __ldg(x + (size_t)row * DIMS + ecol);
                s0 += xv * we1; s1 += xv * we2; s2 += xv * we3;
            }
#pragma unroll
            for (int off = 16; off > 0; off >>= 1) {
                s0 += __shfl_down_sync(0xffffffffu, s0, off);
                s1 += __shfl_down_sync(0xffffffffu, s1, off);
                s2 += __shfl_down_sync(0xffffffffu, s2, off);
            }
            if (lane == 0) {
                g_y1[row] = s0; g_y2[row] = s1; g_y3[row] = s2;
                g_key[row] = f2key(s0);
            }
        }
    }
    unsigned ph = 1;
    gbar(ph);

    // ---------------- phases C: 3 selection rounds ----------------
    const int needs0 = 50000, needs1 = 25000, needs2 = 12500;
    for (int r = 0; r < 3; r++) {
        const int need = (r == 0) ? needs0 : ((r == 1) ? needs1 : needs2);
        unsigned* hist = g_hist[r];

        // C1: 16-bit histogram (skip inactive key==0)
        for (int i = gtid; i < NROWS; i += NB * NT) {
            unsigned key = __ldcg(&g_key[i]);
            if (key) atomicAdd(&hist[key >> 16], 1u);
        }
        gbar(++ph);

        // C2: block 0 scans 65536 bins in descending key order
        if (bid == 0) {
            unsigned base = 65535u - (unsigned)tid * 128u;
            unsigned s = 0;
#pragma unroll 8
            for (int i = 0; i < 128; i++) s += hist[base - i];
            s_scan[tid] = s;
            __syncthreads();
            for (int off = 1; off < NT; off <<= 1) {
                unsigned v = (tid >= off) ? s_scan[tid - off] : 0u;
                __syncthreads();
                s_scan[tid] += v;
                __syncthreads();
            }
            unsigned incl = s_scan[tid], excl = incl - s;
            if ((int)excl < need && need <= (int)incl) {
                unsigned acc = excl;
                for (int i = 0; i < 128; i++) {
                    unsigned c = hist[base - i];
                    if ((int)(acc + c) >= need) {
                        g_Bsel = base - i;
                        g_needB = need - (int)acc;
                        break;
                    }
                    acc += c;
                }
            }
            if (tid == 0) g_ncand = 0;
        }
        gbar(++ph);

        // C3: classify rows; defer exact boundary bucket
        {
            const unsigned Bv = __ldcg(&g_Bsel);
            for (int i = gtid; i < NROWS; i += NB * NT) {
                unsigned key = __ldcg(&g_key[i]);
                if (key) {
                    unsigned b = key >> 16;
                    if (b > Bv) upd(r, i, true, i1, i2, i3);
                    else if (b == Bv) {
                        int ci = atomicAdd(&g_ncand, 1);
                        g_candk[ci] = key; g_candr[ci] = i;
                    } else upd(r, i, false, i1, i2, i3);
                } else upd(r, i, false, i1, i2, i3);
            }
        }
        gbar(++ph);

        // C4: block 0 exact-ranks boundary candidates (tie: lower row first)
        if (bid == 0) {
            int m  = g_ncand;
            int nB = g_needB;
            int mc = (m < CANDCAP) ? m : CANDCAP;
            for (int j = tid; j < mc; j += NT) {
                s_ck[j] = __ldcg(&g_candk[j]);
                s_cr[j] = __ldcg(&g_candr[j]);
            }
            __syncthreads();
            for (int ci = tid; ci < m; ci += NT) {
                unsigned mk = (ci < mc) ? s_ck[ci] : __ldcg(&g_candk[ci]);
                int      mr = (ci < mc) ? s_cr[ci] : __ldcg(&g_candr[ci]);
                int cnt = 0;
                for (int j = 0; j < mc; j++) {
                    unsigned kj = s_ck[j]; int rj = s_cr[j];
                    cnt += (kj > mk || (kj == mk && rj < mr)) ? 1 : 0;
                }
                for (int j = mc; j < m; j++) {
                    unsigned kj = __ldcg(&g_candk[j]); int rj = __ldcg(&g_candr[j]);
                    cnt += (kj > mk || (kj == mk && rj < mr)) ? 1 : 0;
                }
                upd(r, mr, cnt < nB, i1, i2, i3);
            }
            __syncthreads();
        }
        gbar(++ph);
    }

    // ---------------- phase D: weighted gather, row per warp ----------------
    {
        const int a = gw & 3;
        const int e = lane - 8;
        const bool haveE = (e >= 0 && e < 3);
        const int ecol = haveE ? ((e < a) ? e : a + 1440 + (e - a)) : 0;
        float* fp = &g_fpart[gw][0];
#pragma unroll
        for (int h = 0; h < 2; h++) {
            float4 acc[6];
#pragma unroll
            for (int kk = 0; kk < 6; kk++) acc[kk] = make_float4(0.f, 0.f, 0.f, 0.f);
            float accE = 0.f;
            for (int row = gw; row < NROWS; row += TOTW) {
                float c = __ldcg(&g_coef[row]);
                if (c == 0.0f) continue;
                const float4* px = (const float4*)(x + (size_t)row * DIMS + a);
#pragma unroll
                for (int kk = 0; kk < 6; kk++) {
                    int k = h * 6 + kk;
                    if (k < 11 || lane < 8) {
                        int m = lane + 32 * k;
                        float4 v = __ldg(px + m);
                        acc[kk].x += c * v.x; acc[kk].y += c * v.y;
                        acc[kk].z += c * v.z; acc[kk].w += c * v.w;
                    }
                }
                if (h == 1 && haveE) accE += c * __ldg(x + (size_t)row * DIMS + ecol);
            }
#pragma unroll
            for (int kk = 0; kk < 6; kk++) {
                int k = h * 6 + kk;
                if (k < 11 || lane < 8) {
                    int m = lane + 32 * k;
                    int cb = a + 4 * m;
                    fp[cb] = acc[kk].x; fp[cb + 1] = acc[kk].y;
                    fp[cb + 2] = acc[kk].z; fp[cb + 3] = acc[kk].w;
                }
            }
            if (h == 1 && haveE) fp[ecol] = accE;
        }
    }
    gbar(++ph);

    // ---------------- phase E1: reduce 2368 partials -> 16 ----------------
    if (gw < 736) {
        int q = gw & 15, cg = gw >> 4;        // cg in [0,46)
        int col = cg * 32 + lane;
        if (col < DIMS) {
            float s = 0.f;
            int j0 = q * 148;
#pragma unroll 8
            for (int j = j0; j < j0 + 148; j++) s += __ldcg(&g_fpart[j][col]);
            g_epart[q][col] = s;
        }
    }
    gbar(++ph);

    // ---------------- phase E2: 16 -> out ----------------
    if (gw < 46) {
        int col = gw * 32 + lane;
        if (col < DIMS) {
            float s = 0.f;
#pragma unroll
            for (int q = 0; q < 16; q++) s += __ldcg(&g_epart[q][col]);
            out[col] = s;
        }
    }

    // ---- final arrive-only barrier; block 0 resets counter for next replay ----
    __syncthreads();
    if (tid == 0) {
        __threadfence();
        const unsigned tgt = (ph + 1) * NB;
        atomicAdd(&g_bar, 1u);
        if (bid == 0) {
            while (atomicAdd(&g_bar, 0u) < tgt) __nanosleep(128);
            atomicExch(&g_bar, 0u);
            __threadfence();
        }
    }
}

// ---------------- launch ----------------
extern "C" void kernel_launch(void* const* d_in, const int* in_sizes, int n_in,
                              void* d_out, int out_size) {
    const float* x  = (const float*)d_in[0];
    // d_in[1] edge_index, d_in[2] edge_attr: dead inputs
    const float* w1 = (const float*)d_in[3];
    const float* w2 = (const float*)d_in[4];
    const float* w3 = (const float*)d_in[5];
    float* out = (float*)d_out;

    cudaFuncSetAttribute(k_persist, cudaFuncAttributeMaxDynamicSharedMemorySize,
                         WPACK_BYTES);
    k_persist<<<NB, NT, WPACK_BYTES>>>(x, w1, w2, w3, out);
}

// round 3
// speedup vs baseline: 1.3338x; 1.0472x over previous
#include <cuda_runtime.h>
#include <math.h>

#define NROWS 100000
#define DIMS  1443
#define NB    148
#define NT    512
#define NWARP 16
#define TOTW  (NB*NWARP)        // 2368
#define GSTRIDE (NB*NT)
#define WPP   (37*NWARP)        // 592 warps per alignment phase
#define NQUAD 6250              // 25000 rows-per-phase / 4 rows-per-warp-iter
#define JPP   25000
#define SCAP  1024
#define WPACK_BYTES (3*360*16)  // 17280

// ---------------- device scratch (allocation-free) ----------------
__device__ unsigned g_bar = 0;
__device__ float    g_y1[NROWS], g_y2[NROWS], g_y3[NROWS];
__device__ float    g_prod[NROWS];
__device__ float    g_coef[NROWS];
__device__ unsigned g_key[NROWS];
__device__ unsigned g_hist[3][65536];     // zero at entry & exit (replay invariant)
__device__ unsigned g_candk[NROWS];
__device__ int      g_candr[NROWS];
__device__ int      g_ncand;
__device__ unsigned g_Bsel;
__device__ int      g_needB;
__device__ float    g_fpart[TOTW][DIMS];
__device__ float    g_epart[16][DIMS];

__device__ __forceinline__ unsigned f2key(float f) {
    unsigned u = __float_as_uint(f);
    return (u & 0x80000000u) ? ~u : (u | 0x80000000u);   // never 0 for finite f
}

// grid barrier: bar.sync gives intra-block HB; tid0 fence+atomic publishes.
__device__ __forceinline__ void gbar(unsigned ph) {
    __syncthreads();
    if (threadIdx.x == 0) {
        __threadfence();
        atomicAdd(&g_bar, 1u);
        const unsigned tgt = ph * NB;
        while (atomicAdd(&g_bar, 0u) < tgt) __nanosleep(128);
        __threadfence();
    }
    __syncthreads();
}

// per-row round update; returns new key (0 if dropped / r==2)
__device__ __forceinline__ unsigned upd(int r, int i, bool sel,
                                        float i1, float i2, float i3) {
    if (r == 0) {
        if (sel) {
            float s = tanhf(__ldcg(&g_y1[i]) * i1);
            g_prod[i] = s;
            unsigned nk = f2key(s * __ldcg(&g_y2[i]));
            g_key[i] = nk;
            return nk;
        }
        g_key[i] = 0u; return 0u;
    } else if (r == 1) {
        if (sel) {
            float p = __ldcg(&g_prod[i]);
            float s = tanhf(p * __ldcg(&g_y2[i]) * i2);
            p *= s;
            g_prod[i] = p;
            unsigned nk = f2key(p * __ldcg(&g_y3[i]));
            g_key[i] = nk;
            return nk;
        }
        g_key[i] = 0u; return 0u;
    } else {
        float cf = 0.f;
        if (sel) {
            float p = __ldcg(&g_prod[i]);
            float s = tanhf(p * __ldcg(&g_y3[i]) * i3);
            cf = p * s * (1.0f / 12500.0f);
        }
        g_coef[i] = cf;
        return 0u;
    }
}

extern __shared__ float4 s_wp[];   // [3 vecs][360 float4] for this block's phase

__global__ void __launch_bounds__(NT, 2) k_persist(
    const float* __restrict__ x,
    const float* __restrict__ w1, const float* __restrict__ w2,
    const float* __restrict__ w3, float* __restrict__ out)
{
    const int tid  = threadIdx.x, bid = blockIdx.x;
    const int lane = tid & 31,    wid = tid >> 5;
    const int gw   = bid * NWARP + wid;
    const int gtid = bid * NT + tid;
    const int p    = bid & 3;                 // alignment phase of this block
    const int wp   = (bid >> 2) * NWARP + wid; // warp id within phase [0,592)

    __shared__ float    s_n[3][NWARP];
    __shared__ float    s_inv[3];
    __shared__ unsigned s_scan[NT];
    __shared__ unsigned s_ck[SCAP];
    __shared__ int      s_cr[SCAP];

    // ---- w norms (block-local, redundant across blocks) ----
    {
        float a0 = 0.f, a1 = 0.f, a2 = 0.f;
        for (int i = tid; i < DIMS; i += NT) {
            float v1 = __ldg(w1 + i), v2 = __ldg(w2 + i), v3 = __ldg(w3 + i);
            a0 += v1 * v1; a1 += v2 * v2; a2 += v3 * v3;
        }
#pragma unroll
        for (int off = 16; off > 0; off >>= 1) {
            a0 += __shfl_down_sync(0xffffffffu, a0, off);
            a1 += __shfl_down_sync(0xffffffffu, a1, off);
            a2 += __shfl_down_sync(0xffffffffu, a2, off);
        }
        if (lane == 0) { s_n[0][wid] = a0; s_n[1][wid] = a1; s_n[2][wid] = a2; }
    }
    // ---- fill phase-local w-pack ----
    for (int idx = tid; idx < 3 * 360; idx += NT) {
        int v = idx / 360, m = idx % 360;
        const float* w = (v == 0) ? w1 : ((v == 1) ? w2 : w3);
        int col = p + 4 * m;
        s_wp[idx] = make_float4(__ldg(w + col), __ldg(w + col + 1),
                                __ldg(w + col + 2), __ldg(w + col + 3));
    }
    __syncthreads();
    if (tid < 3) {
        float s = 0.f;
        for (int w = 0; w < NWARP; w++) s += s_n[tid][w];
        s_inv[tid] = 1.0f / sqrtf(s);
    }
    __syncthreads();
    const float i1 = s_inv[0], i2 = s_inv[1], i3 = s_inv[2];

    // ---------------- phase B: fused 3-way GEMV, 4 rows per warp-iter ----------------
    {
        const float4* wpa = s_wp;
        const float4* wpb = s_wp + 360;
        const float4* wpc = s_wp + 720;
        const int e = lane - 8;
        const bool haveE = (e >= 0 && e < 3);
        int ecol = 0; float we1 = 0.f, we2 = 0.f, we3 = 0.f;
        if (haveE) {
            ecol = (e < p) ? e : p + 1440 + (e - p);
            we1 = __ldg(w1 + ecol); we2 = __ldg(w2 + ecol); we3 = __ldg(w3 + ecol);
        }
        for (int g = wp; g < NQUAD; g += WPP) {
            const int rbase = p + 16 * g;            // rows rbase, +4, +8, +12
            const float4* px0 = (const float4*)(x + (size_t)(rbase     ) * DIMS + p);
            const float4* px1 = (const float4*)(x + (size_t)(rbase +  4) * DIMS + p);
            const float4* px2 = (const float4*)(x + (size_t)(rbase +  8) * DIMS + p);
            const float4* px3 = (const float4*)(x + (size_t)(rbase + 12) * DIMS + p);
            float acc[12];
#pragma unroll
            for (int v = 0; v < 12; v++) acc[v] = 0.f;
#pragma unroll 4
            for (int k = 0; k < 11; k++) {
                const int m = lane + 32 * k;
                float4 wa = wpa[m], wb = wpb[m], wc = wpc[m];
                float4 v0 = __ldg(px0 + m), v1 = __ldg(px1 + m);
                float4 v2 = __ldg(px2 + m), v3 = __ldg(px3 + m);
                acc[0]  += v0.x*wa.x + v0.y*wa.y + v0.z*wa.z + v0.w*wa.w;
                acc[1]  += v0.x*wb.x + v0.y*wb.y + v0.z*wb.z + v0.w*wb.w;
                acc[2]  += v0.x*wc.x + v0.y*wc.y + v0.z*wc.z + v0.w*wc.w;
                acc[3]  += v1.x*wa.x + v1.y*wa.y + v1.z*wa.z + v1.w*wa.w;
                acc[4]  += v1.x*wb.x + v1.y*wb.y + v1.z*wb.z + v1.w*wb.w;
                acc[5]  += v1.x*wc.x + v1.y*wc.y + v1.z*wc.z + v1.w*wc.w;
                acc[6]  += v2.x*wa.x + v2.y*wa.y + v2.z*wa.z + v2.w*wa.w;
                acc[7]  += v2.x*wb.x + v2.y*wb.y + v2.z*wb.z + v2.w*wb.w;
                acc[8]  += v2.x*wc.x + v2.y*wc.y + v2.z*wc.z + v2.w*wc.w;
                acc[9]  += v3.x*wa.x + v3.y*wa.y + v3.z*wa.z + v3.w*wa.w;
                acc[10] += v3.x*wb.x + v3.y*wb.y + v3.z*wb.z + v3.w*wb.w;
                acc[11] += v3.x*wc.x + v3.y*wc.y + v3.z*wc.z + v3.w*wc.w;
            }
            if (lane < 8) {
                const int m = 352 + lane;
                float4 wa = wpa[m], wb = wpb[m], wc = wpc[m];
                float4 v0 = __ldg(px0 + m), v1 = __ldg(px1 + m);
                float4 v2 = __ldg(px2 + m), v3 = __ldg(px3 + m);
                acc[0]  += v0.x*wa.x + v0.y*wa.y + v0.z*wa.z + v0.w*wa.w;
                acc[1]  += v0.x*wb.x + v0.y*wb.y + v0.z*wb.z + v0.w*wb.w;
                acc[2]  += v0.x*wc.x + v0.y*wc.y + v0.z*wc.z + v0.w*wc.w;
                acc[3]  += v1.x*wa.x + v1.y*wa.y + v1.z*wa.z + v1.w*wa.w;
                acc[4]  += v1.x*wb.x + v1.y*wb.y + v1.z*wb.z + v1.w*wb.w;
                acc[5]  += v1.x*wc.x + v1.y*wc.y + v1.z*wc.z + v1.w*wc.w;
                acc[6]  += v2.x*wa.x + v2.y*wa.y + v2.z*wa.z + v2.w*wa.w;
                acc[7]  += v2.x*wb.x + v2.y*wb.y + v2.z*wb.z + v2.w*wb.w;
                acc[8]  += v2.x*wc.x + v2.y*wc.y + v2.z*wc.z + v2.w*wc.w;
                acc[9]  += v3.x*wa.x + v3.y*wa.y + v3.z*wa.z + v3.w*wa.w;
                acc[10] += v3.x*wb.x + v3.y*wb.y + v3.z*wb.z + v3.w*wb.w;
                acc[11] += v3.x*wc.x + v3.y*wc.y + v3.z*wc.z + v3.w*wc.w;
            }
            if (haveE) {
#pragma unroll
                for (int u = 0; u < 4; u++) {
                    float xv = __ldg(x + (size_t)(rbase + 4 * u) * DIMS + ecol);
                    acc[u * 3 + 0] += xv * we1;
                    acc[u * 3 + 1] += xv * we2;
                    acc[u * 3 + 2] += xv * we3;
                }
            }
#pragma unroll
            for (int off = 16; off > 0; off >>= 1)
#pragma unroll
                for (int v = 0; v < 12; v++)
                    acc[v] += __shfl_down_sync(0xffffffffu, acc[v], off);
            if (lane == 0) {
#pragma unroll
                for (int u = 0; u < 4; u++) {
                    int r = rbase + 4 * u;
                    g_y1[r] = acc[u * 3 + 0];
                    g_y2[r] = acc[u * 3 + 1];
                    g_y3[r] = acc[u * 3 + 2];
                    unsigned key = f2key(acc[u * 3 + 0]);
                    g_key[r] = key;
                    atomicAdd(&g_hist[0][key >> 16], 1u);   // fused round-0 hist
                }
            }
        }
    }
    unsigned ph = 0;
    gbar(++ph);

    // ---------------- selection rounds ----------------
    for (int r = 0; r < 3; r++) {
        const int need = (r == 0) ? 50000 : ((r == 1) ? 25000 : 12500);
        unsigned* hist = g_hist[r];

        // C2: block 0 scans 65536 bins descending
        if (bid == 0) {
            unsigned base = 65535u - (unsigned)tid * 128u;
            unsigned s = 0;
#pragma unroll 8
            for (int i = 0; i < 128; i++) s += __ldcg(&hist[base - i]);
            s_scan[tid] = s;
            __syncthreads();
            for (int off = 1; off < NT; off <<= 1) {
                unsigned v = (tid >= off) ? s_scan[tid - off] : 0u;
                __syncthreads();
                s_scan[tid] += v;
                __syncthreads();
            }
            unsigned incl = s_scan[tid], excl = incl - s;
            if ((int)excl < need && need <= (int)incl) {
                unsigned acc = excl;
                for (int i = 0; i < 128; i++) {
                    unsigned c = __ldcg(&hist[base - i]);
                    if ((int)(acc + c) >= need) {
                        g_Bsel = base - i;
                        g_needB = need - (int)acc;
                        break;
                    }
                    acc += c;
                }
            }
            if (tid == 0) g_ncand = 0;
        }
        gbar(++ph);

        // C3: classify + next-round hist; also re-zero hist[r] (replay invariant)
        {
            const unsigned Bv = __ldcg(&g_Bsel);
            for (int i = gtid; i < 65536; i += GSTRIDE) hist[i] = 0u;
            for (int i = gtid; i < NROWS; i += GSTRIDE) {
                unsigned key = __ldcg(&g_key[i]);
                if (key) {
                    unsigned b = key >> 16;
                    if (b > Bv) {
                        unsigned nk = upd(r, i, true, i1, i2, i3);
                        if (r < 2) atomicAdd(&g_hist[r + 1][nk >> 16], 1u);
                    } else if (b == Bv) {
                        int ci = atomicAdd(&g_ncand, 1);
                        g_candk[ci] = key; g_candr[ci] = i;
                    } else {
                        upd(r, i, false, i1, i2, i3);
                    }
                } else {
                    upd(r, i, false, i1, i2, i3);   // writes coef=0 when r==2
                }
            }
        }
        gbar(++ph);

        // C4: block 0 exact-ranks boundary candidates (tie: lower row first)
        if (bid == 0) {
            int m  = g_ncand;
            int nB = g_needB;
            int mc = (m < SCAP) ? m : SCAP;
            for (int j = tid; j < mc; j += NT) {
                s_ck[j] = __ldcg(&g_candk[j]);
                s_cr[j] = __ldcg(&g_candr[j]);
            }
            __syncthreads();
            for (int ci = tid; ci < m; ci += NT) {
                unsigned mk = (ci < mc) ? s_ck[ci] : __ldcg(&g_candk[ci]);
                int      mr = (ci < mc) ? s_cr[ci] : __ldcg(&g_candr[ci]);
                int cnt = 0;
                for (int j = 0; j < mc; j++) {
                    unsigned kj = s_ck[j]; int rj = s_cr[j];
                    cnt += (kj > mk || (kj == mk && rj < mr)) ? 1 : 0;
                }
                for (int j = mc; j < m; j++) {
                    unsigned kj = __ldcg(&g_candk[j]); int rj = __ldcg(&g_candr[j]);
                    cnt += (kj > mk || (kj == mk && rj < mr)) ? 1 : 0;
                }
                bool sel = (cnt < nB);
                unsigned nk = upd(r, mr, sel, i1, i2, i3);
                if (r < 2 && sel) atomicAdd(&g_hist[r + 1][nk >> 16], 1u);
            }
            __syncthreads();
        }
        gbar(++ph);
    }

    // ---------------- phase D: weighted gather, row per warp ----------------
    {
        const int e = lane - 8;
        const bool haveE = (e >= 0 && e < 3);
        const int ecol = haveE ? ((e < p) ? e : p + 1440 + (e - p)) : 0;
        float* fp = &g_fpart[gw][0];
#pragma unroll
        for (int h = 0; h < 2; h++) {
            float4 acc[6];
#pragma unroll
            for (int kk = 0; kk < 6; kk++) acc[kk] = make_float4(0.f, 0.f, 0.f, 0.f);
            float accE = 0.f;
            for (int jj = wp; jj < JPP; jj += WPP) {
                int row = p + 4 * jj;
                float c = __ldcg(&g_coef[row]);
                if (c == 0.0f) continue;
                const float4* px = (const float4*)(x + (size_t)row * DIMS + p);
#pragma unroll
                for (int kk = 0; kk < 6; kk++) {
                    int k = h * 6 + kk;
                    if (k < 11 || lane < 8) {
                        float4 v = __ldg(px + lane + 32 * k);
                        acc[kk].x += c * v.x; acc[kk].y += c * v.y;
                        acc[kk].z += c * v.z; acc[kk].w += c * v.w;
                    }
                }
                if (h == 1 && haveE) accE += c * __ldg(x + (size_t)row * DIMS + ecol);
            }
#pragma unroll
            for (int kk = 0; kk < 6; kk++) {
                int k = h * 6 + kk;
                if (k < 11 || lane < 8) {
                    int m = lane + 32 * k;
                    int cb = p + 4 * m;
                    fp[cb] = acc[kk].x; fp[cb + 1] = acc[kk].y;
                    fp[cb + 2] = acc[kk].z; fp[cb + 3] = acc[kk].w;
                }
            }
            if (h == 1 && haveE) fp[ecol] = accE;
        }
    }
    gbar(++ph);

    // ---------------- E1: reduce 2368 partials -> 16 ----------------
    if (gw < 736) {
        int q = gw & 15, cg = gw >> 4;
        int col = cg * 32 + lane;
        if (col < DIMS) {
            float s = 0.f;
            int j0 = q * 148;
#pragma unroll 8
            for (int j = j0; j < j0 + 148; j++) s += __ldcg(&g_fpart[j][col]);
            g_epart[q][col] = s;
        }
    }
    gbar(++ph);

    // ---------------- E2: 16 -> out ----------------
    if (gw < 46) {
        int col = gw * 32 + lane;
        if (col < DIMS) {
            float s = 0.f;
#pragma unroll
            for (int q = 0; q < 16; q++) s += __ldcg(&g_epart[q][col]);
            out[col] = s;
        }
    }

    // ---- final arrive-only barrier; block 0 resets counter for next replay ----
    __syncthreads();
    if (tid == 0) {
        __threadfence();
        const unsigned tgt = (ph + 1) * NB;
        atomicAdd(&g_bar, 1u);
        if (bid == 0) {
            while (atomicAdd(&g_bar, 0u) < tgt) __nanosleep(128);
            atomicExch(&g_bar, 0u);
            __threadfence();
        }
    }
}

// ---------------- launch ----------------
extern "C" void kernel_launch(void* const* d_in, const int* in_sizes, int n_in,
                              void* d_out, int out_size) {
    const float* x  = (const float*)d_in[0];
    // d_in[1] edge_index, d_in[2] edge_attr: dead inputs
    const float* w1 = (const float*)d_in[3];
    const float* w2 = (const float*)d_in[4];
    const float* w3 = (const float*)d_in[5];
    float* out = (float*)d_out;

    cudaFuncSetAttribute(k_persist, cudaFuncAttributeMaxDynamicSharedMemorySize,
                         WPACK_BYTES);
    k_persist<<<NB, NT, WPACK_BYTES>>>(x, w1, w2, w3, out);
}

// round 4
// speedup vs baseline: 1.5941x; 1.1951x over previous
#include <cuda_runtime.h>
#include <math.h>

#define NROWS 100000
#define DIMS  1443
#define NB    148
#define NT    1024
#define NWARP 32
#define TOTW  (NB*NWARP)        // 4736
#define GSTRIDE (NB*NT)
#define WPP   (37*NWARP)        // 1184 warps per alignment phase
#define NQUAD 6250              // 25000 rows-per-phase / 4 rows-per-warp-iter
#define JPP   25000
#define SCAP  1024
#define WPACK_BYTES (3*360*16)  // 17280

// ---------------- device scratch (allocation-free) ----------------
__device__ unsigned g_bar = 0;
__device__ float    g_y1[NROWS], g_y2[NROWS], g_y3[NROWS];
__device__ float    g_prod[NROWS];
__device__ float    g_coef[NROWS];
__device__ unsigned g_key[NROWS];
__device__ unsigned g_hist[3][65536];     // zero at entry & exit (replay invariant)
__device__ unsigned g_candk[NROWS];
__device__ int      g_candr[NROWS];
__device__ int      g_ncand;
__device__ unsigned g_Bsel;
__device__ int      g_needB;
__device__ float    g_fpart[TOTW][DIMS];
__device__ float    g_epart[16][DIMS];

__device__ __forceinline__ unsigned f2key(float f) {
    unsigned u = __float_as_uint(f);
    return (u & 0x80000000u) ? ~u : (u | 0x80000000u);   // never 0 for finite f
}

// grid barrier: bar.sync gives intra-block HB; tid0 fence+atomic publishes.
__device__ __forceinline__ void gbar(unsigned ph) {
    __syncthreads();
    if (threadIdx.x == 0) {
        __threadfence();
        atomicAdd(&g_bar, 1u);
        const unsigned tgt = ph * NB;
        while (atomicAdd(&g_bar, 0u) < tgt) __nanosleep(128);
        __threadfence();
    }
    __syncthreads();
}

// per-row round update; returns new key (0 if dropped / r==2)
__device__ __forceinline__ unsigned upd(int r, int i, bool sel,
                                        float i1, float i2, float i3) {
    if (r == 0) {
        if (sel) {
            float s = tanhf(__ldcg(&g_y1[i]) * i1);
            g_prod[i] = s;
            unsigned nk = f2key(s * __ldcg(&g_y2[i]));
            g_key[i] = nk;
            return nk;
        }
        g_key[i] = 0u; return 0u;
    } else if (r == 1) {
        if (sel) {
            float p = __ldcg(&g_prod[i]);
            float s = tanhf(p * __ldcg(&g_y2[i]) * i2);
            p *= s;
            g_prod[i] = p;
            unsigned nk = f2key(p * __ldcg(&g_y3[i]));
            g_key[i] = nk;
            return nk;
        }
        g_key[i] = 0u; return 0u;
    } else {
        float cf = 0.f;
        if (sel) {
            float p = __ldcg(&g_prod[i]);
            float s = tanhf(p * __ldcg(&g_y3[i]) * i3);
            cf = p * s * (1.0f / 12500.0f);
        }
        g_coef[i] = cf;
        return 0u;
    }
}

extern __shared__ float4 s_wp[];   // [3 vecs][360 float4] for this block's phase

__global__ void __launch_bounds__(NT, 1) k_persist(
    const float* __restrict__ x,
    const float* __restrict__ w1, const float* __restrict__ w2,
    const float* __restrict__ w3, float* __restrict__ out)
{
    const int tid  = threadIdx.x, bid = blockIdx.x;
    const int lane = tid & 31,    wid = tid >> 5;
    const int gw   = bid * NWARP + wid;
    const int gtid = bid * NT + tid;
    const int p    = bid & 3;                  // alignment phase of this block
    const int wp   = (bid >> 2) * NWARP + wid; // warp id within phase [0,1184)

    __shared__ float    s_n[3][NWARP];
    __shared__ float    s_inv[3];
    __shared__ unsigned s_scan[NT];
    __shared__ unsigned s_ck[SCAP];
    __shared__ int      s_cr[SCAP];

    // ---- w norms (block-local, redundant across blocks) ----
    {
        float a0 = 0.f, a1 = 0.f, a2 = 0.f;
        for (int i = tid; i < DIMS; i += NT) {
            float v1 = __ldg(w1 + i), v2 = __ldg(w2 + i), v3 = __ldg(w3 + i);
            a0 += v1 * v1; a1 += v2 * v2; a2 += v3 * v3;
        }
#pragma unroll
        for (int off = 16; off > 0; off >>= 1) {
            a0 += __shfl_down_sync(0xffffffffu, a0, off);
            a1 += __shfl_down_sync(0xffffffffu, a1, off);
            a2 += __shfl_down_sync(0xffffffffu, a2, off);
        }
        if (lane == 0) { s_n[0][wid] = a0; s_n[1][wid] = a1; s_n[2][wid] = a2; }
    }
    // ---- fill phase-local w-pack ----
    for (int idx = tid; idx < 3 * 360; idx += NT) {
        int v = idx / 360, m = idx % 360;
        const float* w = (v == 0) ? w1 : ((v == 1) ? w2 : w3);
        int col = p + 4 * m;
        s_wp[idx] = make_float4(__ldg(w + col), __ldg(w + col + 1),
                                __ldg(w + col + 2), __ldg(w + col + 3));
    }
    __syncthreads();
    if (tid < 3) {
        float s = 0.f;
        for (int w = 0; w < NWARP; w++) s += s_n[tid][w];
        s_inv[tid] = 1.0f / sqrtf(s);
    }
    __syncthreads();
    const float i1 = s_inv[0], i2 = s_inv[1], i3 = s_inv[2];

    // ---------------- phase B: fused 3-way GEMV, 4 rows per warp-iter ----------------
    {
        const float4* wpa = s_wp;
        const float4* wpb = s_wp + 360;
        const float4* wpc = s_wp + 720;
        const int e = lane - 8;
        const bool haveE = (e >= 0 && e < 3);
        int ecol = 0; float we1 = 0.f, we2 = 0.f, we3 = 0.f;
        if (haveE) {
            ecol = (e < p) ? e : p + 1440 + (e - p);
            we1 = __ldg(w1 + ecol); we2 = __ldg(w2 + ecol); we3 = __ldg(w3 + ecol);
        }
        for (int g = wp; g < NQUAD; g += WPP) {
            const int rbase = p + 16 * g;            // rows rbase, +4, +8, +12
            const float4* px0 = (const float4*)(x + (size_t)(rbase     ) * DIMS + p);
            const float4* px1 = (const float4*)(x + (size_t)(rbase +  4) * DIMS + p);
            const float4* px2 = (const float4*)(x + (size_t)(rbase +  8) * DIMS + p);
            const float4* px3 = (const float4*)(x + (size_t)(rbase + 12) * DIMS + p);
            float acc[12];
#pragma unroll
            for (int v = 0; v < 12; v++) acc[v] = 0.f;
#pragma unroll 4
            for (int k = 0; k < 11; k++) {
                const int m = lane + 32 * k;
                float4 wa = wpa[m], wb = wpb[m], wc = wpc[m];
                float4 v0 = __ldg(px0 + m), v1 = __ldg(px1 + m);
                float4 v2 = __ldg(px2 + m), v3 = __ldg(px3 + m);
                acc[0]  += v0.x*wa.x + v0.y*wa.y + v0.z*wa.z + v0.w*wa.w;
                acc[1]  += v0.x*wb.x + v0.y*wb.y + v0.z*wb.z + v0.w*wb.w;
                acc[2]  += v0.x*wc.x + v0.y*wc.y + v0.z*wc.z + v0.w*wc.w;
                acc[3]  += v1.x*wa.x + v1.y*wa.y + v1.z*wa.z + v1.w*wa.w;
                acc[4]  += v1.x*wb.x + v1.y*wb.y + v1.z*wb.z + v1.w*wb.w;
                acc[5]  += v1.x*wc.x + v1.y*wc.y + v1.z*wc.z + v1.w*wc.w;
                acc[6]  += v2.x*wa.x + v2.y*wa.y + v2.z*wa.z + v2.w*wa.w;
                acc[7]  += v2.x*wb.x + v2.y*wb.y + v2.z*wb.z + v2.w*wb.w;
                acc[8]  += v2.x*wc.x + v2.y*wc.y + v2.z*wc.z + v2.w*wc.w;
                acc[9]  += v3.x*wa.x + v3.y*wa.y + v3.z*wa.z + v3.w*wa.w;
                acc[10] += v3.x*wb.x + v3.y*wb.y + v3.z*wb.z + v3.w*wb.w;
                acc[11] += v3.x*wc.x + v3.y*wc.y + v3.z*wc.z + v3.w*wc.w;
            }
            if (lane < 8) {
                const int m = 352 + lane;
                float4 wa = wpa[m], wb = wpb[m], wc = wpc[m];
                float4 v0 = __ldg(px0 + m), v1 = __ldg(px1 + m);
                float4 v2 = __ldg(px2 + m), v3 = __ldg(px3 + m);
                acc[0]  += v0.x*wa.x + v0.y*wa.y + v0.z*wa.z + v0.w*wa.w;
                acc[1]  += v0.x*wb.x + v0.y*wb.y + v0.z*wb.z + v0.w*wb.w;
                acc[2]  += v0.x*wc.x + v0.y*wc.y + v0.z*wc.z + v0.w*wc.w;
                acc[3]  += v1.x*wa.x + v1.y*wa.y + v1.z*wa.z + v1.w*wa.w;
                acc[4]  += v1.x*wb.x + v1.y*wb.y + v1.z*wb.z + v1.w*wb.w;
                acc[5]  += v1.x*wc.x + v1.y*wc.y + v1.z*wc.z + v1.w*wc.w;
                acc[6]  += v2.x*wa.x + v2.y*wa.y + v2.z*wa.z + v2.w*wa.w;
                acc[7]  += v2.x*wb.x + v2.y*wb.y + v2.z*wb.z + v2.w*wb.w;
                acc[8]  += v2.x*wc.x + v2.y*wc.y + v2.z*wc.z + v2.w*wc.w;
                acc[9]  += v3.x*wa.x + v3.y*wa.y + v3.z*wa.z + v3.w*wa.w;
                acc[10] += v3.x*wb.x + v3.y*wb.y + v3.z*wb.z + v3.w*wb.w;
                acc[11] += v3.x*wc.x + v3.y*wc.y + v3.z*wc.z + v3.w*wc.w;
            }
            if (haveE) {
#pragma unroll
                for (int u = 0; u < 4; u++) {
                    float xv = __ldg(x + (size_t)(rbase + 4 * u) * DIMS + ecol);
                    acc[u * 3 + 0] += xv * we1;
                    acc[u * 3 + 1] += xv * we2;
                    acc[u * 3 + 2] += xv * we3;
                }
            }
#pragma unroll
            for (int off = 16; off > 0; off >>= 1)
#pragma unroll
                for (int v = 0; v < 12; v++)
                    acc[v] += __shfl_down_sync(0xffffffffu, acc[v], off);
            if (lane == 0) {
#pragma unroll
                for (int u = 0; u < 4; u++) {
                    int r = rbase + 4 * u;
                    g_y1[r] = acc[u * 3 + 0];
                    g_y2[r] = acc[u * 3 + 1];
                    g_y3[r] = acc[u * 3 + 2];
                    unsigned key = f2key(acc[u * 3 + 0]);
                    g_key[r] = key;
                    atomicAdd(&g_hist[0][key >> 16], 1u);   // fused round-0 hist
                }
            }
        }
    }
    unsigned ph = 0;
    gbar(++ph);

    // ---------------- selection rounds ----------------
    for (int r = 0; r < 3; r++) {
        const int need = (r == 0) ? 50000 : ((r == 1) ? 25000 : 12500);
        unsigned* hist = g_hist[r];

        // C2: block 0 scans 65536 bins descending
        if (bid == 0) {
            unsigned base = 65535u - (unsigned)tid * 64u;
            unsigned s = 0;
#pragma unroll 8
            for (int i = 0; i < 64; i++) s += __ldcg(&hist[base - i]);
            s_scan[tid] = s;
            __syncthreads();
            for (int off = 1; off < NT; off <<= 1) {
                unsigned v = (tid >= off) ? s_scan[tid - off] : 0u;
                __syncthreads();
                s_scan[tid] += v;
                __syncthreads();
            }
            unsigned incl = s_scan[tid], excl = incl - s;
            if ((int)excl < need && need <= (int)incl) {
                unsigned acc = excl;
                for (int i = 0; i < 64; i++) {
                    unsigned c = __ldcg(&hist[base - i]);
                    if ((int)(acc + c) >= need) {
                        g_Bsel = base - i;
                        g_needB = need - (int)acc;
                        break;
                    }
                    acc += c;
                }
            }
            if (tid == 0) g_ncand = 0;
        }
        gbar(++ph);

        // C3: classify + next-round hist; also re-zero hist[r] (replay invariant)
        {
            const unsigned Bv = __ldcg(&g_Bsel);
            for (int i = gtid; i < 65536; i += GSTRIDE) hist[i] = 0u;
            for (int i = gtid; i < NROWS; i += GSTRIDE) {
                unsigned key = __ldcg(&g_key[i]);
                if (key) {
                    unsigned b = key >> 16;
                    if (b > Bv) {
                        unsigned nk = upd(r, i, true, i1, i2, i3);
                        if (r < 2) atomicAdd(&g_hist[r + 1][nk >> 16], 1u);
                    } else if (b == Bv) {
                        int ci = atomicAdd(&g_ncand, 1);
                        g_candk[ci] = key; g_candr[ci] = i;
                    } else {
                        upd(r, i, false, i1, i2, i3);
                    }
                } else {
                    upd(r, i, false, i1, i2, i3);   // writes coef=0 when r==2
                }
            }
        }
        gbar(++ph);

        // C4: block 0 exact-ranks boundary candidates (tie: lower row first)
        if (bid == 0) {
            int m  = g_ncand;
            int nB = g_needB;
            int mc = (m < SCAP) ? m : SCAP;
            for (int j = tid; j < mc; j += NT) {
                s_ck[j] = __ldcg(&g_candk[j]);
                s_cr[j] = __ldcg(&g_candr[j]);
            }
            __syncthreads();
            for (int ci = tid; ci < m; ci += NT) {
                unsigned mk = (ci < mc) ? s_ck[ci] : __ldcg(&g_candk[ci]);
                int      mr = (ci < mc) ? s_cr[ci] : __ldcg(&g_candr[ci]);
                int cnt = 0;
                for (int j = 0; j < mc; j++) {
                    unsigned kj = s_ck[j]; int rj = s_cr[j];
                    cnt += (kj > mk || (kj == mk && rj < mr)) ? 1 : 0;
                }
                for (int j = mc; j < m; j++) {
                    unsigned kj = __ldcg(&g_candk[j]); int rj = __ldcg(&g_candr[j]);
                    cnt += (kj > mk || (kj == mk && rj < mr)) ? 1 : 0;
                }
                bool sel = (cnt < nB);
                unsigned nk = upd(r, mr, sel, i1, i2, i3);
                if (r < 2 && sel) atomicAdd(&g_hist[r + 1][nk >> 16], 1u);
            }
            __syncthreads();
        }
        gbar(++ph);
    }

    // ---------------- phase D: weighted gather, row per warp ----------------
    {
        const int e = lane - 8;
        const bool haveE = (e >= 0 && e < 3);
        const int ecol = haveE ? ((e < p) ? e : p + 1440 + (e - p)) : 0;
        float* fp = &g_fpart[gw][0];
#pragma unroll
        for (int h = 0; h < 2; h++) {
            float4 acc[6];
#pragma unroll
            for (int kk = 0; kk < 6; kk++) acc[kk] = make_float4(0.f, 0.f, 0.f, 0.f);
            float accE = 0.f;
            for (int jj = wp; jj < JPP; jj += WPP) {
                int row = p + 4 * jj;
                float c = __ldcg(&g_coef[row]);
                if (c == 0.0f) continue;
                const float4* px = (const float4*)(x + (size_t)row * DIMS + p);
#pragma unroll
                for (int kk = 0; kk < 6; kk++) {
                    int k = h * 6 + kk;
                    if (k < 11 || lane < 8) {
                        float4 v = __ldg(px + lane + 32 * k);
                        acc[kk].x += c * v.x; acc[kk].y += c * v.y;
                        acc[kk].z += c * v.z; acc[kk].w += c * v.w;
                    }
                }
                if (h == 1 && haveE) accE += c * __ldg(x + (size_t)row * DIMS + ecol);
            }
#pragma unroll
            for (int kk = 0; kk < 6; kk++) {
                int k = h * 6 + kk;
                if (k < 11 || lane < 8) {
                    int m = lane + 32 * k;
                    int cb = p + 4 * m;
                    fp[cb] = acc[kk].x; fp[cb + 1] = acc[kk].y;
                    fp[cb + 2] = acc[kk].z; fp[cb + 3] = acc[kk].w;
                }
            }
            if (h == 1 && haveE) fp[ecol] = accE;
        }
    }
    gbar(++ph);

    // ---------------- E1: reduce 4736 partials -> 16 ----------------
    if (gw < 736) {
        int q = gw & 15, cg = gw >> 4;
        int col = cg * 32 + lane;
        if (col < DIMS) {
            float s = 0.f;
            int j0 = q * (TOTW / 16);
#pragma unroll 8
            for (int j = j0; j < j0 + (TOTW / 16); j++) s += __ldcg(&g_fpart[j][col]);
            g_epart[q][col] = s;
        }
    }
    gbar(++ph);

    // ---------------- E2: 16 -> out ----------------
    if (gw < 46) {
        int col = gw * 32 + lane;
        if (col < DIMS) {
            float s = 0.f;
#pragma unroll
            for (int q = 0; q < 16; q++) s += __ldcg(&g_epart[q][col]);
            out[col] = s;
        }
    }

    // ---- final arrive-only barrier; block 0 resets counter for next replay ----
    __syncthreads();
    if (tid == 0) {
        __threadfence();
        const unsigned tgt = (ph + 1) * NB;
        atomicAdd(&g_bar, 1u);
        if (bid == 0) {
            while (atomicAdd(&g_bar, 0u) < tgt) __nanosleep(128);
            atomicExch(&g_bar, 0u);
            __threadfence();
        }
    }
}

// ---------------- launch ----------------
extern "C" void kernel_launch(void* const* d_in, const int* in_sizes, int n_in,
                              void* d_out, int out_size) {
    const float* x  = (const float*)d_in[0];
    // d_in[1] edge_index, d_in[2] edge_attr: dead inputs
    const float* w1 = (const float*)d_in[3];
    const float* w2 = (const float*)d_in[4];
    const float* w3 = (const float*)d_in[5];
    float* out = (float*)d_out;

    cudaFuncSetAttribute(k_persist, cudaFuncAttributeMaxDynamicSharedMemorySize,
                         WPACK_BYTES);
    k_persist<<<NB, NT, WPACK_BYTES>>>(x, w1, w2, w3, out);
}